// round 1
// baseline (speedup 1.0000x reference)
#include <cuda_runtime.h>

// dcn_56925496541545: 3x (sparse 9x9 neighbor-mean stencil -> convex combo -> sigmoid),
// output = x[:,0]. Inputs: d_in[0] = x [N,9] f32, d_in[1] = w1 [1] f32. Out: [N] f32.

#define THREADS 256

__device__ __forceinline__ float sigmoid_half_arg(float t_half) {
    // sigmoid(t) = 0.5*tanh(t/2) + 0.5 ; caller passes t/2 (halves folded into weights)
    float th;
    asm("tanh.approx.f32 %0, %1;" : "=f"(th) : "f"(t_half));
    return fmaf(0.5f, th, 0.5f);
}

__global__ __launch_bounds__(THREADS)
void dcn_56925496541545_kernel(const float* __restrict__ x,
                               const float* __restrict__ w1p,
                               float* __restrict__ out,
                               int n)  // number of patches
{
    __shared__ float sx[THREADS * 9];  // 9216 B

    const int patch0 = blockIdx.x * THREADS;      // first patch of this block
    const long long baseF = (long long)patch0 * 9;  // first float of this block
    const long long totalF = (long long)n * 9;

    // ---- Stage 256 patches (2304 floats) into shared via float4 (fully coalesced) ----
    if (baseF + THREADS * 9 <= totalF) {
        const float4* gx = reinterpret_cast<const float4*>(x + baseF);  // 16B aligned: baseF*4 = blk*9216
        float4* s4 = reinterpret_cast<float4*>(sx);
        #pragma unroll
        for (int i = threadIdx.x; i < (THREADS * 9) / 4; i += THREADS)
            s4[i] = gx[i];
    } else {
        // tail block (not hit for N=4M, but stay shape-generic)
        for (int i = threadIdx.x; i < THREADS * 9; i += THREADS) {
            long long g = baseF + i;
            sx[i] = (g < totalF) ? x[g] : 0.0f;
        }
    }

    const float w1 = __ldg(w1p);
    const float w2 = 1.0f - w1;
    // fold the 0.5 (for tanh form) and the 1/len stencil normalization into the weights
    const float h1 = 0.5f * w1;
    const float h3 = 0.5f * w2 * (1.0f / 3.0f);
    const float h5 = 0.5f * w2 * (1.0f / 5.0f);
    const float h8 = 0.5f * w2 * (1.0f / 8.0f);

    __syncthreads();

    const int patch = patch0 + threadIdx.x;
    if (patch >= n) return;

    const float* a = &sx[threadIdx.x * 9];  // stride-9 shared reads: conflict-free (gcd(9,32)=1)
    float a0 = a[0], a1 = a[1], a2 = a[2],
          a3 = a[3], a4 = a[4], a5 = a[5],
          a6 = a[6], a7 = a[7], a8 = a[8];

    // two full iterations (all 9 elements live)
    #pragma unroll
    for (int it = 0; it < 2; ++it) {
        // shared pair sums
        const float p14 = a1 + a4, p34 = a3 + a4, p45 = a4 + a5, p47 = a4 + a7;
        const float q02 = a0 + a2, q06 = a0 + a6, q28 = a2 + a8, q68 = a6 + a8;
        // neighbor sums (normalization folded into h3/h5/h8)
        const float b00 = p34 + a1;
        const float b02 = p14 + a5;
        const float b20 = p34 + a7;
        const float b22 = p45 + a7;
        const float b01 = (q02 + p34) + a5;
        const float b10 = (q06 + p14) + a7;
        const float b12 = (q28 + p47) + a1;
        const float b21 = (q68 + p45) + a3;
        const float s   = ((b01 + a1) + a7) + q68;   // sum of all 9
        const float b11 = s - a4;

        a0 = sigmoid_half_arg(fmaf(h1, a0, h3 * b00));
        a1 = sigmoid_half_arg(fmaf(h1, a1, h5 * b01));
        a2 = sigmoid_half_arg(fmaf(h1, a2, h3 * b02));
        a3 = sigmoid_half_arg(fmaf(h1, a3, h5 * b10));
        a4 = sigmoid_half_arg(fmaf(h1, a4, h8 * b11));
        a5 = sigmoid_half_arg(fmaf(h1, a5, h5 * b12));
        a6 = sigmoid_half_arg(fmaf(h1, a6, h3 * b20));
        a7 = sigmoid_half_arg(fmaf(h1, a7, h5 * b21));
        a8 = sigmoid_half_arg(fmaf(h1, a8, h3 * b22));
    }

    // third iteration: only element 0 of the output is consumed
    const float b00 = (a1 + a3) + a4;
    out[patch] = sigmoid_half_arg(fmaf(h1, a0, h3 * b00));
}

extern "C" void kernel_launch(void* const* d_in, const int* in_sizes, int n_in,
                              void* d_out, int out_size) {
    const float* x   = (const float*)d_in[0];
    const float* w1  = (const float*)d_in[1];
    float* out       = (float*)d_out;
    const int n      = in_sizes[0] / 9;  // number of patches

    const int blocks = (n + THREADS - 1) / THREADS;
    dcn_56925496541545_kernel<<<blocks, THREADS>>>(x, w1, out, n);
}

// round 2
// speedup vs baseline: 1.2604x; 1.2604x over previous
#include <cuda_runtime.h>
#include <cstdint>

// dcn_56925496541545: 3x (sparse 9x9 neighbor-mean stencil -> convex combo -> sigmoid),
// output = x[:,0]. Inputs: d_in[0] = x [N,9] f32, d_in[1] = w1 [1] f32. Out: [N] f32.
//
// R2: dead-code-eliminated iterations (9+4+1 sigmoids instead of 9+9+1),
//     IPT=4 with cp.async staging (9 back-to-back 16B cp.async per thread).

#define THREADS 256
#define IPT 4
#define PPB (THREADS * IPT)   // patches per block = 1024

__device__ __forceinline__ float sigmoid_half_arg(float t_half) {
    // sigmoid(t) = 0.5*tanh(t/2) + 0.5 ; caller passes t/2 (halves folded into weights)
    float th;
    asm("tanh.approx.f32 %0, %1;" : "=f"(th) : "f"(t_half));
    return fmaf(0.5f, th, 0.5f);
}

__global__ __launch_bounds__(THREADS, 3)
void dcn_56925496541545_kernel(const float* __restrict__ x,
                               const float* __restrict__ w1p,
                               float* __restrict__ out,
                               int n)  // number of patches
{
    __shared__ float sx[PPB * 9];  // 36864 B

    const long long patch0 = (long long)blockIdx.x * PPB;
    const long long baseF  = patch0 * 9;

    // ---- Stage 1024 patches (9216 floats) into shared ----
    if (patch0 + PPB <= (long long)n) {
        // full block: 2304 float4s, 9 per thread, issued back-to-back (no dest regs)
        uint32_t s_base = (uint32_t)__cvta_generic_to_shared(sx);
        const float4* g = reinterpret_cast<const float4*>(x + baseF);  // 16B aligned: baseF*4 = blk*36864
        #pragma unroll
        for (int k = 0; k < 9; ++k) {
            int i = threadIdx.x + k * THREADS;
            uint32_t saddr = s_base + i * 16u;
            asm volatile("cp.async.cg.shared.global [%0], [%1], 16;\n"
                         :: "r"(saddr), "l"(g + i));
        }
        asm volatile("cp.async.commit_group;\n"
                     "cp.async.wait_group 0;\n" ::: "memory");
    } else {
        // tail block: guarded scalar loads
        const long long totalF = (long long)n * 9;
        for (int i = threadIdx.x; i < PPB * 9; i += THREADS) {
            long long gidx = baseF + i;
            sx[i] = (gidx < totalF) ? x[gidx] : 0.0f;
        }
    }

    const float w1 = __ldg(w1p);
    const float w2 = 1.0f - w1;
    // fold 0.5 (tanh form) and stencil normalization into weights
    const float h1 = 0.5f * w1;
    const float h3 = 0.5f * w2 * (1.0f / 3.0f);
    const float h5 = 0.5f * w2 * (1.0f / 5.0f);
    const float h8 = 0.5f * w2 * (1.0f / 8.0f);

    __syncthreads();

    #pragma unroll
    for (int k = 0; k < IPT; ++k) {
        const int  lp = threadIdx.x + k * THREADS;         // local patch id
        const long long p = patch0 + lp;                   // global patch id
        if (p < (long long)n) {
            const float* a = &sx[lp * 9];  // stride-9 shared reads: conflict-free
            float a0 = a[0], a1 = a[1], a2 = a[2],
                  a3 = a[3], a4 = a[4], a5 = a[5],
                  a6 = a[6], a7 = a[7], a8 = a[8];

            // ---- iteration 1: all 9 elements live ----
            {
                const float p14 = a1 + a4, p34 = a3 + a4, p45 = a4 + a5, p47 = a4 + a7;
                const float q02 = a0 + a2, q06 = a0 + a6, q28 = a2 + a8, q68 = a6 + a8;
                const float b00 = p34 + a1;
                const float b02 = p14 + a5;
                const float b20 = p34 + a7;
                const float b22 = p45 + a7;
                const float b01 = (q02 + p34) + a5;
                const float b10 = (q06 + p14) + a7;
                const float b12 = (q28 + p47) + a1;
                const float b21 = (q68 + p45) + a3;
                const float s   = ((b01 + a1) + a7) + q68;   // sum of all 9
                const float b11 = s - a4;

                a0 = sigmoid_half_arg(fmaf(h1, a0, h3 * b00));
                a1 = sigmoid_half_arg(fmaf(h1, a1, h5 * b01));
                a2 = sigmoid_half_arg(fmaf(h1, a2, h3 * b02));
                a3 = sigmoid_half_arg(fmaf(h1, a3, h5 * b10));
                a4 = sigmoid_half_arg(fmaf(h1, a4, h8 * b11));
                a5 = sigmoid_half_arg(fmaf(h1, a5, h5 * b12));
                a6 = sigmoid_half_arg(fmaf(h1, a6, h3 * b20));
                a7 = sigmoid_half_arg(fmaf(h1, a7, h5 * b21));
                a8 = sigmoid_half_arg(fmaf(h1, a8, h3 * b22));
            }

            // ---- iteration 2: only elements {0,1,3,4} are live downstream ----
            float c0, c1, c3, c4;
            {
                const float p34 = a3 + a4;
                const float b00 = p34 + a1;
                const float b01 = ((a0 + a2) + p34) + a5;
                const float b10 = ((a0 + a6) + (a1 + a4)) + a7;
                const float s   = (((b01 + a1) + a7) + a6) + a8;  // sum of all 9
                const float b11 = s - a4;

                c0 = sigmoid_half_arg(fmaf(h1, a0, h3 * b00));
                c1 = sigmoid_half_arg(fmaf(h1, a1, h5 * b01));
                c3 = sigmoid_half_arg(fmaf(h1, a3, h5 * b10));
                c4 = sigmoid_half_arg(fmaf(h1, a4, h8 * b11));
            }

            // ---- iteration 3: only element 0 is consumed ----
            const float b00 = (c1 + c3) + c4;
            out[p] = sigmoid_half_arg(fmaf(h1, c0, h3 * b00));
        }
    }
}

extern "C" void kernel_launch(void* const* d_in, const int* in_sizes, int n_in,
                              void* d_out, int out_size) {
    const float* x   = (const float*)d_in[0];
    const float* w1  = (const float*)d_in[1];
    float* out       = (float*)d_out;
    const int n      = in_sizes[0] / 9;  // number of patches

    const int blocks = (int)(((long long)n + PPB - 1) / PPB);
    dcn_56925496541545_kernel<<<blocks, THREADS>>>(x, w1, out, n);
}

// round 3
// speedup vs baseline: 1.3600x; 1.0790x over previous
#include <cuda_runtime.h>
#include <cstdint>

// dcn_56925496541545: 3x (sparse 9x9 neighbor-mean stencil -> convex combo -> sigmoid),
// output = x[:,0]. Inputs: d_in[0] = x [N,9] f32, d_in[1] = w1 [1] f32. Out: [N] f32.
//
// R3: per-chunk pipelined cp.async staging (4 commit groups, progressive
//     wait_group 3..0), DCE'd iterations (9+4+1 sigmoids), unguarded fast path.

#define THREADS 256
#define IPT 4
#define PPB (THREADS * IPT)            // patches per block = 1024
#define F4_PER_CHUNK ((THREADS * 9) / 4)  // 576 float4 per 256-patch chunk

__device__ __forceinline__ float sigmoid_half_arg(float t_half) {
    // sigmoid(t) = 0.5*tanh(t/2) + 0.5 ; caller passes t/2 (halves folded into weights)
    float th;
    asm("tanh.approx.f32 %0, %1;" : "=f"(th) : "f"(t_half));
    return fmaf(0.5f, th, 0.5f);
}

// Full 3-iteration patch evaluation with dead-code elimination:
// iter1 keeps all 9, iter2 keeps {0,1,3,4}, iter3 keeps {0}.
__device__ __forceinline__ float patch_eval(const float* __restrict__ a,
                                            float h1, float h3, float h5, float h8) {
    float a0 = a[0], a1 = a[1], a2 = a[2],
          a3 = a[3], a4 = a[4], a5 = a[5],
          a6 = a[6], a7 = a[7], a8 = a[8];

    // ---- iteration 1: all 9 live ----
    {
        const float p14 = a1 + a4, p34 = a3 + a4, p45 = a4 + a5, p47 = a4 + a7;
        const float q02 = a0 + a2, q06 = a0 + a6, q28 = a2 + a8, q68 = a6 + a8;
        const float b00 = p34 + a1;
        const float b02 = p14 + a5;
        const float b20 = p34 + a7;
        const float b22 = p45 + a7;
        const float b01 = (q02 + p34) + a5;
        const float b10 = (q06 + p14) + a7;
        const float b12 = (q28 + p47) + a1;
        const float b21 = (q68 + p45) + a3;
        const float s   = ((b01 + a1) + a7) + q68;   // sum of all 9
        const float b11 = s - a4;

        a0 = sigmoid_half_arg(fmaf(h1, a0, h3 * b00));
        a1 = sigmoid_half_arg(fmaf(h1, a1, h5 * b01));
        a2 = sigmoid_half_arg(fmaf(h1, a2, h3 * b02));
        a3 = sigmoid_half_arg(fmaf(h1, a3, h5 * b10));
        a4 = sigmoid_half_arg(fmaf(h1, a4, h8 * b11));
        a5 = sigmoid_half_arg(fmaf(h1, a5, h5 * b12));
        a6 = sigmoid_half_arg(fmaf(h1, a6, h3 * b20));
        a7 = sigmoid_half_arg(fmaf(h1, a7, h5 * b21));
        a8 = sigmoid_half_arg(fmaf(h1, a8, h3 * b22));
    }

    // ---- iteration 2: only {0,1,3,4} live ----
    float c0, c1, c3, c4;
    {
        const float p34 = a3 + a4;
        const float b00 = p34 + a1;
        const float b01 = ((a0 + a2) + p34) + a5;
        const float b10 = ((a0 + a6) + (a1 + a4)) + a7;
        const float s   = (((b01 + a1) + a7) + a6) + a8;  // sum of all 9
        const float b11 = s - a4;

        c0 = sigmoid_half_arg(fmaf(h1, a0, h3 * b00));
        c1 = sigmoid_half_arg(fmaf(h1, a1, h5 * b01));
        c3 = sigmoid_half_arg(fmaf(h1, a3, h5 * b10));
        c4 = sigmoid_half_arg(fmaf(h1, a4, h8 * b11));
    }

    // ---- iteration 3: only element 0 consumed ----
    const float b00 = (c1 + c3) + c4;
    return sigmoid_half_arg(fmaf(h1, c0, h3 * b00));
}

__global__ __launch_bounds__(THREADS, 3)
void dcn_56925496541545_kernel(const float* __restrict__ x,
                               const float* __restrict__ w1p,
                               float* __restrict__ out,
                               int n)  // number of patches
{
    __shared__ float sx[PPB * 9];  // 36864 B

    const long long patch0 = (long long)blockIdx.x * PPB;
    const long long baseF  = patch0 * 9;
    const int tid = threadIdx.x;

    const float w1 = __ldg(w1p);   // issue early; overlaps with cp.async setup
    const bool full = (patch0 + PPB <= (long long)n);

    const uint32_t s_base = (uint32_t)__cvta_generic_to_shared(sx);

    if (full) {
        // ---- issue 4 commit groups, one per 256-patch chunk (9216 B each) ----
        const float4* g = reinterpret_cast<const float4*>(x + baseF);  // 16B aligned
        #pragma unroll
        for (int c = 0; c < IPT; ++c) {
            const int b4 = c * F4_PER_CHUNK;
            {
                int i = b4 + tid;
                asm volatile("cp.async.cg.shared.global [%0], [%1], 16;\n"
                             :: "r"(s_base + i * 16u), "l"(g + i));
            }
            {
                int i = b4 + tid + THREADS;
                asm volatile("cp.async.cg.shared.global [%0], [%1], 16;\n"
                             :: "r"(s_base + i * 16u), "l"(g + i));
            }
            if (tid < F4_PER_CHUNK - 2 * THREADS) {   // 64 threads carry the 3rd float4
                int i = b4 + tid + 2 * THREADS;
                asm volatile("cp.async.cg.shared.global [%0], [%1], 16;\n"
                             :: "r"(s_base + i * 16u), "l"(g + i));
            }
            asm volatile("cp.async.commit_group;\n" ::: "memory");
        }
    } else {
        // tail block: guarded scalar loads, single barrier, guarded compute below
        const long long totalF = (long long)n * 9;
        for (int i = tid; i < PPB * 9; i += THREADS) {
            long long gidx = baseF + i;
            sx[i] = (gidx < totalF) ? x[gidx] : 0.0f;
        }
    }

    const float w2 = 1.0f - w1;
    const float h1 = 0.5f * w1;
    const float h3 = 0.5f * w2 * (1.0f / 3.0f);
    const float h5 = 0.5f * w2 * (1.0f / 5.0f);
    const float h8 = 0.5f * w2 * (1.0f / 8.0f);

    if (full) {
        // ---- pipelined consume: chunk c computes while chunks c+1.. are in flight ----
        #define CONSUME_CHUNK(C, WAITN)                                              \
            {                                                                        \
                asm volatile("cp.async.wait_group %0;\n" :: "n"(WAITN) : "memory");  \
                __syncthreads();                                                     \
                const int lp = tid + (C) * THREADS;                                  \
                out[patch0 + lp] = patch_eval(&sx[lp * 9], h1, h3, h5, h8);          \
            }
        CONSUME_CHUNK(0, 3)
        CONSUME_CHUNK(1, 2)
        CONSUME_CHUNK(2, 1)
        CONSUME_CHUNK(3, 0)
        #undef CONSUME_CHUNK
    } else {
        __syncthreads();
        #pragma unroll
        for (int c = 0; c < IPT; ++c) {
            const int lp = tid + c * THREADS;
            const long long p = patch0 + lp;
            if (p < (long long)n)
                out[p] = patch_eval(&sx[lp * 9], h1, h3, h5, h8);
        }
    }
}

extern "C" void kernel_launch(void* const* d_in, const int* in_sizes, int n_in,
                              void* d_out, int out_size) {
    const float* x   = (const float*)d_in[0];
    const float* w1  = (const float*)d_in[1];
    float* out       = (float*)d_out;
    const int n      = in_sizes[0] / 9;  // number of patches

    const int blocks = (int)(((long long)n + PPB - 1) / PPB);
    dcn_56925496541545_kernel<<<blocks, THREADS>>>(x, w1, out, n);
}